// round 6
// baseline (speedup 1.0000x reference)
#include <cuda_runtime.h>
#include <cooperative_groups.h>

namespace cg = cooperative_groups;

#define BATCH   64
#define NGT     1024
#define MPRED   2048
#define THRESH2 256.0f    // 16.0^2
#define GDIM    32        // 32x32 grid of 16px cells (512 / 16)
#define NCELL   (GDIM * GDIM)
#define TPB     512
#define RANKS   4

// Cluster of 4 CTAs (512 threads each) per batch; grid = 256, 2 CTAs/SM.
// Each CTA independently bins the batch's 1024 gts (2/thread) into a 32x32
// cell CSR in its own smem, then scans 512 preds (rank r -> preds
// [r*512, r*512+512)) against the 3x3 cell neighborhood. Exactly equivalent
// to the full argmin: matches only matter under the 16px threshold, and any
// gt within 16px lies in the 3x3 neighborhood of the pred's cell.
// All ranks atomicMin (gt -> min pred index) into RANK 0's s_best via DSMEM;
// cluster.sync() orders the remote atomics; rank 0 does the fused gather.
// d2 uses __fadd_rn/__fmul_rn (no FMA) -> bit-identical to the reference;
// tie rule (equal d2 -> lower gt index) is explicit, so all atomic/scan
// orderings are result-invariant.
__global__ __launch_bounds__(TPB, 2) __cluster_dims__(RANKS, 1, 1)
void lacss_match_kernel(
    const float2* __restrict__ gt,    // [BATCH, NGT]
    const float2* __restrict__ pred,  // [BATCH, MPRED]
    float2* __restrict__ out)         // [BATCH, NGT]
{
    __shared__ int    s_cnt[NCELL];      // counts, then scatter cursor
    __shared__ int    s_off[NCELL + 1];  // exclusive CSR offsets
    __shared__ float4 s_pt[NGT];         // {gx, gy, idx-as-float, pad} binned
    __shared__ int    s_best[NGT];       // min matched pred j per gt (rank0 authoritative)
    __shared__ int    s_wsum[32];

    cg::cluster_group cluster = cg::this_cluster();
    const unsigned rank = cluster.block_rank();

    const int b    = blockIdx.x >> 2;
    const int tid  = threadIdx.x;
    const int lane = tid & 31;
    const int wid  = tid >> 5;           // 16 warps

    // ---- prefetch ALL global inputs up front (MLP=3, DRAM latency hidden
    //      behind the binning phase) ----
    const int j = (int)rank * TPB + tid;           // this thread's pred
    const float2 p  = pred[b * MPRED + j];
    const float2 g0 = gt[b * NGT + tid];
    const float2 g1 = gt[b * NGT + TPB + tid];

    s_cnt[tid]        = 0;
    s_cnt[tid + TPB]  = 0;
    s_best[tid]       = MPRED;           // sentinel: unmatched
    s_best[tid + TPB] = MPRED;
    __syncthreads();

    // ---- count (cell = y/16 * 32 + x/16; *2^-4 exact) ----
    const int c0 = (int)(g0.y * 0.0625f) * GDIM + (int)(g0.x * 0.0625f);
    const int c1 = (int)(g1.y * 0.0625f) * GDIM + (int)(g1.x * 0.0625f);
    atomicAdd(&s_cnt[c0], 1);
    atomicAdd(&s_cnt[c1], 1);
    __syncthreads();

    // ---- exclusive prefix sum over 1024 cells, 2 cells/thread ----
    const int a0 = s_cnt[2 * tid];
    const int a1 = s_cnt[2 * tid + 1];
    const int v  = a0 + a1;
    int inc = v;
    #pragma unroll
    for (int d = 1; d < 32; d <<= 1) {
        int n = __shfl_up_sync(0xFFFFFFFFu, inc, d);
        if (lane >= d) inc += n;
    }
    if (lane == 31) s_wsum[wid] = inc;
    __syncthreads();
    if (wid == 0) {
        int w  = (lane < 16) ? s_wsum[lane] : 0;
        int wi = w;
        #pragma unroll
        for (int d = 1; d < 32; d <<= 1) {
            int n = __shfl_up_sync(0xFFFFFFFFu, wi, d);
            if (lane >= d) wi += n;
        }
        if (lane < 16) s_wsum[lane] = wi - w;    // exclusive warp offset
    }
    __syncthreads();
    const int excl = (inc - v) + s_wsum[wid];
    s_off[2 * tid]     = excl;
    s_off[2 * tid + 1] = excl + a0;
    if (tid == 0) s_off[NCELL] = NGT;
    // cursor = copy of exclusive offsets (write to s_cnt, no extra sync
    // needed before the one below)
    s_cnt[2 * tid]     = excl;
    s_cnt[2 * tid + 1] = excl + a0;
    __syncthreads();

    // ---- scatter both gts into binned order, idx packed into .z ----
    {
        int p0 = atomicAdd(&s_cnt[c0], 1);
        s_pt[p0] = make_float4(g0.x, g0.y, __int_as_float(tid), 0.f);
        int p1 = atomicAdd(&s_cnt[c1], 1);
        s_pt[p1] = make_float4(g1.x, g1.y, __int_as_float(tid + TPB), 0.f);
    }
    __syncthreads();

    // ---- pred phase: one pred per thread, 3x3 neighborhood (3 runs) ----
    {
        const int pcx = (int)(p.x * 0.0625f);
        const int pcy = (int)(p.y * 0.0625f);
        const int x0 = max(pcx - 1, 0), x1 = min(pcx + 1, GDIM - 1);
        const int y0 = max(pcy - 1, 0), y1 = min(pcy + 1, GDIM - 1);

        float best = THRESH2;            // strict < doubles as threshold test
        int   bi   = -1;

        for (int cy = y0; cy <= y1; cy++) {
            const int ks = s_off[cy * GDIM + x0];
            const int ke = s_off[cy * GDIM + x1 + 1];   // cells contiguous in x
            for (int k = ks; k < ke; k++) {
                float4 q = s_pt[k];                     // one LDS.128
                int   gi = __float_as_int(q.z);
                float dx = __fadd_rn(p.x, -q.x);
                float dy = __fadd_rn(p.y, -q.y);
                float d2 = __fadd_rn(__fmul_rn(dx, dx), __fmul_rn(dy, dy));
                bool take = (d2 < best) || (d2 == best && gi < bi);
                bi   = take ? gi : bi;
                best = take ? d2 : best;
            }
        }

        if (bi >= 0) {
            int* dst = (rank == 0) ? s_best
                                   : cluster.map_shared_rank(s_best, 0);
            atomicMin(&dst[bi], j);
        }
    }

    cluster.sync();                      // orders remote atomics before gather

    // ---- fused gather by rank 0 (2 outputs per thread) ----
    if (rank == 0) {
        int s0 = s_best[tid];
        int s1 = s_best[tid + TPB];
        out[b * NGT + tid]       = (s0 < MPRED) ? pred[b * MPRED + s0] : g0;
        out[b * NGT + TPB + tid] = (s1 < MPRED) ? pred[b * MPRED + s1] : g1;
    }
}

extern "C" void kernel_launch(void* const* d_in, const int* in_sizes, int n_in,
                              void* d_out, int out_size) {
    const float2* gt   = (const float2*)d_in[0];   // gt_locations   [64,1024,2] f32
    const float2* pred = (const float2*)d_in[1];   // pred_locations [64,2048,2] f32
    float2* out = (float2*)d_out;                  // [64,1024,2] f32

    lacss_match_kernel<<<BATCH * RANKS, TPB>>>(gt, pred, out);
}

// round 7
// speedup vs baseline: 1.1228x; 1.1228x over previous
#include <cuda_runtime.h>
#include <cooperative_groups.h>

namespace cg = cooperative_groups;

#define BATCH   64
#define NGT     1024
#define MPRED   2048
#define THRESH2 256.0f    // 16.0^2
#define GDIM    32        // 32x32 grid of 16px cells (512 / 16)
#define NCELL   (GDIM * GDIM)

// Cluster of 2 CTAs (1024 threads) per batch; grid = 128 (148 = 2*74 packs
// perfectly; cluster-4 strands SMs and quadruples duplicated binning — R6
// regression). Each CTA independently bins the batch's 1024 gts into a 32x32
// cell CSR in its own smem, then scans 1024 preds (rank r -> preds
// [r*1024, ...)) against the 3x3 cell neighborhood. Exactly equivalent to the
// full argmin: matches only matter under the 16px threshold, and any gt
// within 16px of a pred lies in the 3x3 neighborhood of the pred's cell.
// Both ranks atomicMin (gt -> min pred index) into RANK 0's s_best (DSMEM for
// rank 1); cluster.sync() orders the remote atomics; rank 0 does the fused
// gather. One launch, no global scratch.
// d2 uses __fadd_rn/__fmul_rn (no FMA) -> bit-identical to the reference;
// the tie rule (equal d2 -> lower gt index) is explicit, so scatter and
// atomic orderings are result-invariant.
__global__ __launch_bounds__(1024, 1) __cluster_dims__(2, 1, 1)
void lacss_match_kernel(
    const float2* __restrict__ gt,    // [BATCH, NGT]
    const float2* __restrict__ pred,  // [BATCH, MPRED]
    float2* __restrict__ out)         // [BATCH, NGT]
{
    __shared__ int    s_cnt[NCELL];      // counts, then scatter cursor
    __shared__ int    s_off[NCELL + 1];  // exclusive CSR offsets
    __shared__ float4 s_pt[NGT];         // {gx, gy, idx-as-float, pad} binned
    __shared__ int    s_best[NGT];       // min matched pred j per gt (rank0 authoritative)
    __shared__ int    s_wsum[32];

    cg::cluster_group cluster = cg::this_cluster();
    const unsigned rank = cluster.block_rank();

    const int b    = blockIdx.x >> 1;
    const int tid  = threadIdx.x;
    const int lane = tid & 31;
    const int wid  = tid >> 5;

    // ---- prefetch BOTH global inputs up front (MLP=2): the pred's 577-cyc
    //      DRAM latency hides behind the entire binning phase ----
    const int j = (int)rank * 1024 + tid;          // this thread's pred
    const float2 p = pred[b * MPRED + j];
    const float2 g = gt[b * NGT + tid];

    s_cnt[tid]  = 0;
    s_best[tid] = MPRED;                 // sentinel: unmatched
    __syncthreads();

    // ---- count (cell = y/16 * 32 + x/16; *2^-4 exact) ----
    const int gcell = (int)(g.y * 0.0625f) * GDIM + (int)(g.x * 0.0625f);
    atomicAdd(&s_cnt[gcell], 1);
    __syncthreads();

    // ---- exclusive prefix sum of s_cnt -> s_off ----
    int v   = s_cnt[tid];
    int inc = v;
    #pragma unroll
    for (int d = 1; d < 32; d <<= 1) {
        int n = __shfl_up_sync(0xFFFFFFFFu, inc, d);
        if (lane >= d) inc += n;
    }
    if (lane == 31) s_wsum[wid] = inc;
    __syncthreads();
    if (wid == 0) {
        int w  = s_wsum[lane];
        int wi = w;
        #pragma unroll
        for (int d = 1; d < 32; d <<= 1) {
            int n = __shfl_up_sync(0xFFFFFFFFu, wi, d);
            if (lane >= d) wi += n;
        }
        s_wsum[lane] = wi - w;           // exclusive offset of warp `lane`
    }
    __syncthreads();
    const int excl = (inc - v) + s_wsum[wid];
    s_off[tid] = excl;
    if (tid == 0) s_off[NCELL] = NGT;
    s_cnt[tid] = excl;                   // cursor = copy of offsets
    __syncthreads();

    // ---- scatter gts into binned order, original idx packed into .z ----
    {
        int pos = atomicAdd(&s_cnt[gcell], 1);
        s_pt[pos] = make_float4(g.x, g.y, __int_as_float(tid), 0.f);
    }
    __syncthreads();

    // ---- pred phase: one pred per thread, 3x3 neighborhood (3 runs) ----
    {
        const int pcx = (int)(p.x * 0.0625f);
        const int pcy = (int)(p.y * 0.0625f);
        const int x0 = max(pcx - 1, 0), x1 = min(pcx + 1, GDIM - 1);
        const int y0 = max(pcy - 1, 0), y1 = min(pcy + 1, GDIM - 1);

        float best = THRESH2;            // strict < doubles as threshold test
        int   bi   = -1;

        for (int cy = y0; cy <= y1; cy++) {
            const int ks = s_off[cy * GDIM + x0];
            const int ke = s_off[cy * GDIM + x1 + 1];   // cells contiguous in x
            for (int k = ks; k < ke; k++) {
                float4 q = s_pt[k];                     // one LDS.128
                int   gi = __float_as_int(q.z);
                float dx = __fadd_rn(p.x, -q.x);
                float dy = __fadd_rn(p.y, -q.y);
                float d2 = __fadd_rn(__fmul_rn(dx, dx), __fmul_rn(dy, dy));
                bool take = (d2 < best) || (d2 == best && gi < bi);
                bi   = take ? gi : bi;
                best = take ? d2 : best;
            }
        }

        if (bi >= 0) {
            int* dst = (rank == 0) ? s_best
                                   : cluster.map_shared_rank(s_best, 0);
            atomicMin(&dst[bi], j);
        }
    }

    cluster.sync();                      // orders remote atomics before gather

    // ---- fused gather by rank 0 ----
    if (rank == 0) {
        const int s = s_best[tid];
        out[b * NGT + tid] = (s < MPRED) ? pred[b * MPRED + s] : g;
    }
}

extern "C" void kernel_launch(void* const* d_in, const int* in_sizes, int n_in,
                              void* d_out, int out_size) {
    const float2* gt   = (const float2*)d_in[0];   // gt_locations   [64,1024,2] f32
    const float2* pred = (const float2*)d_in[1];   // pred_locations [64,2048,2] f32
    float2* out = (float2*)d_out;                  // [64,1024,2] f32

    lacss_match_kernel<<<BATCH * 2, 1024>>>(gt, pred, out);
}